// round 1
// baseline (speedup 1.0000x reference)
#include <cuda_runtime.h>
#include <math.h>

// Problem constants (fixed by the dataset)
#define NMAX 50000
#define EMAX 400000
#define ETMAX (NMAX + EMAX)   // edges + self loops
#define HEADS 4
#define HID 128

// ---------------- static scratch (no allocations allowed) ----------------
__device__ __align__(16) float g_Hbuf[(size_t)NMAX * 512];   // GEMM output h (pre-aggregation)
__device__ __align__(16) float g_ACT [(size_t)NMAX * 512];   // aggregated + elu activations
__device__ __align__(16) float g_as[NMAX * HEADS];
__device__ __align__(16) float g_ad[NMAX * HEADS];
__device__ __align__(16) float g_w [(size_t)ETMAX * HEADS];  // per-edge-per-head softmax weights
__device__ int g_deg[NMAX];
__device__ int g_incl[NMAX];
__device__ int g_bsum[64];
__device__ int g_boff[64];
__device__ int g_rowptr[NMAX + 1];
__device__ int g_col[ETMAX];
__device__ int g_widx[NMAX];

// ---------------- CSR construction ----------------
__global__ void k_init_deg(int N) {
    int i = blockIdx.x * blockDim.x + threadIdx.x;
    if (i < N) g_deg[i] = 1;   // self-loop
}
__global__ void k_count(const int* __restrict__ dst, int E) {
    int i = blockIdx.x * blockDim.x + threadIdx.x;
    if (i < E) atomicAdd(&g_deg[dst[i]], 1);
}
__global__ void k_scan1(int N) {
    __shared__ int sh[1024];
    int i = blockIdx.x * 1024 + threadIdx.x;
    int v = (i < N) ? g_deg[i] : 0;
    sh[threadIdx.x] = v;
    __syncthreads();
    for (int off = 1; off < 1024; off <<= 1) {
        int u = (threadIdx.x >= off) ? sh[threadIdx.x - off] : 0;
        __syncthreads();
        sh[threadIdx.x] += u;
        __syncthreads();
    }
    if (i < N) g_incl[i] = sh[threadIdx.x];
    if (threadIdx.x == 1023) g_bsum[blockIdx.x] = sh[1023];
}
__global__ void k_scan2(int nb) {
    __shared__ int sh[64];
    int t = threadIdx.x;
    int v = (t < nb) ? g_bsum[t] : 0;
    sh[t] = v;
    __syncthreads();
    for (int off = 1; off < 64; off <<= 1) {
        int u = (t >= off) ? sh[t - off] : 0;
        __syncthreads();
        sh[t] += u;
        __syncthreads();
    }
    g_boff[t] = sh[t] - v;   // exclusive prefix of block sums
}
__global__ void k_scan3(int N) {
    int i = blockIdx.x * blockDim.x + threadIdx.x;
    if (i < N) {
        g_rowptr[i + 1] = g_incl[i] + g_boff[i >> 10];
        if (i == 0) g_rowptr[0] = 0;
    }
}
__global__ void k_fill_self(int N) {
    int i = blockIdx.x * blockDim.x + threadIdx.x;
    if (i < N) { g_col[g_rowptr[i]] = i; g_widx[i] = 1; }
}
__global__ void k_fill_edges(const int* __restrict__ src, const int* __restrict__ dst, int E) {
    int i = blockIdx.x * blockDim.x + threadIdx.x;
    if (i < E) {
        int d = dst[i];
        int p = atomicAdd(&g_widx[d], 1);
        g_col[g_rowptr[d] + p] = src[i];
    }
}

// ---------------- dense GEMM: C[N,M] = A[N,K] @ B[K,M] ----------------
// 128x128 tile, BK=8, 256 threads, 8x8 per thread. M % 128 == 0, K % 8 == 0.
__global__ __launch_bounds__(256) void k_sgemm(const float* __restrict__ A,
                                               const float* __restrict__ B,
                                               float* __restrict__ C,
                                               int N, int K, int M) {
    __shared__ float As[8][128];
    __shared__ float Bs[8][128];
    int tid = threadIdx.x;
    int tx = tid & 15, ty = tid >> 4;
    int row0 = blockIdx.y * 128, col0 = blockIdx.x * 128;
    float acc[8][8];
#pragma unroll
    for (int i = 0; i < 8; i++)
#pragma unroll
        for (int j = 0; j < 8; j++) acc[i][j] = 0.f;

    int aRow = tid >> 1, aCol = (tid & 1) * 4;
    int bRow = tid >> 5, bCol = (tid & 31) * 4;

    for (int k0 = 0; k0 < K; k0 += 8) {
        float4 av = make_float4(0.f, 0.f, 0.f, 0.f);
        int r = row0 + aRow;
        if (r < N) av = *(const float4*)(A + (size_t)r * K + k0 + aCol);
        As[aCol + 0][aRow] = av.x;
        As[aCol + 1][aRow] = av.y;
        As[aCol + 2][aRow] = av.z;
        As[aCol + 3][aRow] = av.w;
        float4 bv = *(const float4*)(B + (size_t)(k0 + bRow) * M + col0 + bCol);
        *(float4*)&Bs[bRow][bCol] = bv;
        __syncthreads();
#pragma unroll
        for (int k = 0; k < 8; k++) {
            float a[8], b[8];
#pragma unroll
            for (int i = 0; i < 8; i++) a[i] = As[k][ty * 8 + i];
#pragma unroll
            for (int j = 0; j < 8; j++) b[j] = Bs[k][tx * 8 + j];
#pragma unroll
            for (int i = 0; i < 8; i++)
#pragma unroll
                for (int j = 0; j < 8; j++) acc[i][j] = fmaf(a[i], b[j], acc[i][j]);
        }
        __syncthreads();
    }
#pragma unroll
    for (int i = 0; i < 8; i++) {
        int r = row0 + ty * 8 + i;
        if (r < N) {
            float* cp = C + (size_t)r * M + col0 + tx * 8;
            *(float4*)cp       = make_float4(acc[i][0], acc[i][1], acc[i][2], acc[i][3]);
            *(float4*)(cp + 4) = make_float4(acc[i][4], acc[i][5], acc[i][6], acc[i][7]);
        }
    }
}

// ---------------- per-(node,head) attention scalars ----------------
template <int H>
__global__ void k_alpha(const float* __restrict__ h,
                        const float* __restrict__ a_src,
                        const float* __restrict__ a_dst, int N) {
    int w = blockIdx.x * (blockDim.x >> 5) + (threadIdx.x >> 5);
    int lane = threadIdx.x & 31;
    if (w >= N * H) return;
    int n = w / H, hd = w % H;
    const float* row = h + (size_t)n * (H * HID) + hd * HID;
    float s1 = 0.f, s2 = 0.f;
#pragma unroll
    for (int c = lane; c < HID; c += 32) {
        float v = row[c];
        s1 = fmaf(v, a_src[hd * HID + c], s1);
        s2 = fmaf(v, a_dst[hd * HID + c], s2);
    }
    for (int off = 16; off; off >>= 1) {
        s1 += __shfl_xor_sync(0xffffffffu, s1, off);
        s2 += __shfl_xor_sync(0xffffffffu, s2, off);
    }
    if (lane == 0) { g_as[w] = s1; g_ad[w] = s2; }
}

// ---------------- per-node segment softmax over incoming edges ----------------
template <int H>
__global__ void k_softmax(int N) {
    int n = blockIdx.x * (blockDim.x >> 5) + (threadIdx.x >> 5);
    int lane = threadIdx.x & 31;
    if (n >= N) return;
    int beg = g_rowptr[n], end = g_rowptr[n + 1];
    float adh[H], mx[H], sm[H];
#pragma unroll
    for (int h = 0; h < H; h++) {
        adh[h] = g_ad[n * H + h];
        mx[h] = -1e30f;
        sm[h] = 0.f;
    }
    for (int j = beg + lane; j < end; j += 32) {
        int s = g_col[j];
#pragma unroll
        for (int h = 0; h < H; h++) {
            float e = g_as[s * H + h] + adh[h];
            e = e > 0.f ? e : 0.2f * e;           // leaky relu
            g_w[(size_t)j * H + h] = e;
            mx[h] = fmaxf(mx[h], e);
        }
    }
#pragma unroll
    for (int h = 0; h < H; h++)
        for (int off = 16; off; off >>= 1)
            mx[h] = fmaxf(mx[h], __shfl_xor_sync(0xffffffffu, mx[h], off));
    for (int j = beg + lane; j < end; j += 32) {
#pragma unroll
        for (int h = 0; h < H; h++) {
            float ex = __expf(g_w[(size_t)j * H + h] - mx[h]);
            g_w[(size_t)j * H + h] = ex;
            sm[h] += ex;
        }
    }
#pragma unroll
    for (int h = 0; h < H; h++) {
        for (int off = 16; off; off >>= 1)
            sm[h] += __shfl_xor_sync(0xffffffffu, sm[h], off);
        sm[h] = 1.f / sm[h];
    }
    for (int j = beg + lane; j < end; j += 32) {
#pragma unroll
        for (int h = 0; h < H; h++) g_w[(size_t)j * H + h] *= sm[h];
    }
}

// ---------------- per-node weighted gather-aggregate + bias + elu ----------------
template <int H>
__global__ __launch_bounds__(128) void k_aggregate(const float* __restrict__ hbuf,
                                                   const float* __restrict__ bias,
                                                   float* __restrict__ out, int N) {
    int n = blockIdx.x;
    if (n >= N) return;
    int t = threadIdx.x;   // 128
    float acc[H];
#pragma unroll
    for (int k = 0; k < H; k++) acc[k] = 0.f;
    int beg = g_rowptr[n], end = g_rowptr[n + 1];
    for (int j = beg; j < end; j++) {
        int s = g_col[j];
        const float* hr = hbuf + (size_t)s * (H * HID);
        if (H == 4) {
            float4 w4 = *(const float4*)(g_w + (size_t)j * 4);
            acc[0] = fmaf(w4.x, hr[t], acc[0]);
            acc[1] = fmaf(w4.y, hr[t + 128], acc[1]);
            acc[2] = fmaf(w4.z, hr[t + 256], acc[2]);
            acc[3] = fmaf(w4.w, hr[t + 384], acc[3]);
        } else {
            float ww = g_w[j];
            acc[0] = fmaf(ww, hr[t], acc[0]);
        }
    }
#pragma unroll
    for (int k = 0; k < H; k++) {
        int c = t + 128 * k;
        float v = acc[k] + bias[c];
        out[(size_t)n * (H * HID) + c] = v > 0.f ? v : (__expf(v) - 1.f);   // elu
    }
}

// ---------------- fc head: relu(x@fc1+b1) @ fc2 + b2 -> sigmoid ----------------
__global__ __launch_bounds__(64) void k_fc(const float* __restrict__ act,
                                           const float* __restrict__ w1,
                                           const float* __restrict__ b1,
                                           const float* __restrict__ w2,
                                           const float* __restrict__ b2,
                                           float* __restrict__ out, int N) {
    __shared__ float xs[128];
    __shared__ float part[2];
    int n = blockIdx.x;
    int t = threadIdx.x;   // 64
    xs[t]      = act[(size_t)n * 128 + t];
    xs[t + 64] = act[(size_t)n * 128 + t + 64];
    __syncthreads();
    float d = b1[t];
#pragma unroll 8
    for (int k = 0; k < 128; k++) d = fmaf(xs[k], w1[k * 64 + t], d);
    d = fmaxf(d, 0.f);
    float p = d * w2[t];
    for (int off = 16; off; off >>= 1) p += __shfl_xor_sync(0xffffffffu, p, off);
    if ((t & 31) == 0) part[t >> 5] = p;
    __syncthreads();
    if (t == 0) out[n] = 1.f / (1.f + __expf(-(part[0] + part[1] + b2[0])));
}

// ---------------- launch ----------------
extern "C" void kernel_launch(void* const* d_in, const int* in_sizes, int n_in,
                              void* d_out, int out_size) {
    const float* x      = (const float*)d_in[0];
    const int*   eidx   = (const int*)d_in[1];
    const float* W1     = (const float*)d_in[2];
    const float* a_src1 = (const float*)d_in[3];
    const float* a_dst1 = (const float*)d_in[4];
    const float* b1     = (const float*)d_in[5];
    const float* W2     = (const float*)d_in[6];
    const float* a_src2 = (const float*)d_in[7];
    const float* a_dst2 = (const float*)d_in[8];
    const float* b2     = (const float*)d_in[9];
    const float* W3     = (const float*)d_in[10];
    const float* a_src3 = (const float*)d_in[11];
    const float* a_dst3 = (const float*)d_in[12];
    const float* b3     = (const float*)d_in[13];
    const float* fc1w   = (const float*)d_in[14];
    const float* fc1b   = (const float*)d_in[15];
    const float* fc2w   = (const float*)d_in[16];
    const float* fc2b   = (const float*)d_in[17];
    float* out = (float*)d_out;

    int N = in_sizes[0] / 64;
    int E = in_sizes[1] / 2;
    const int* srcp = eidx;
    const int* dstp = eidx + E;

    float *Hb, *ACT;
    cudaGetSymbolAddress((void**)&Hb, g_Hbuf);
    cudaGetSymbolAddress((void**)&ACT, g_ACT);

    int nb = (N + 1023) / 1024;

    // CSR (dst-indexed) with self-loops
    k_init_deg<<<(N + 255) / 256, 256>>>(N);
    k_count<<<(E + 255) / 256, 256>>>(dstp, E);
    k_scan1<<<nb, 1024>>>(N);
    k_scan2<<<1, 64>>>(nb);
    k_scan3<<<(N + 255) / 256, 256>>>(N);
    k_fill_self<<<(N + 255) / 256, 256>>>(N);
    k_fill_edges<<<(E + 255) / 256, 256>>>(srcp, dstp, E);

    dim3 blk(256);
    // Layer 1: h = x @ W1  [N,512]
    k_sgemm<<<dim3(512 / 128, (N + 127) / 128), blk>>>(x, W1, Hb, N, 64, 512);
    k_alpha<4><<<(N * 4 + 7) / 8, 256>>>(Hb, a_src1, a_dst1, N);
    k_softmax<4><<<(N + 7) / 8, 256>>>(N);
    k_aggregate<4><<<N, 128>>>(Hb, b1, ACT, N);

    // Layer 2
    k_sgemm<<<dim3(512 / 128, (N + 127) / 128), blk>>>(ACT, W2, Hb, N, 512, 512);
    k_alpha<4><<<(N * 4 + 7) / 8, 256>>>(Hb, a_src2, a_dst2, N);
    k_softmax<4><<<(N + 7) / 8, 256>>>(N);
    k_aggregate<4><<<N, 128>>>(Hb, b2, ACT, N);

    // Layer 3 (heads=1)
    k_sgemm<<<dim3(128 / 128, (N + 127) / 128), blk>>>(ACT, W3, Hb, N, 512, 128);
    k_alpha<1><<<(N + 7) / 8, 256>>>(Hb, a_src3, a_dst3, N);
    k_softmax<1><<<(N + 7) / 8, 256>>>(N);
    k_aggregate<1><<<N, 128>>>(Hb, b3, ACT, N);

    // MLP head
    k_fc<<<N, 64>>>(ACT, fc1w, fc1b, fc2w, fc2b, out, N);
}

// round 3
// speedup vs baseline: 1.4657x; 1.4657x over previous
#include <cuda_runtime.h>
#include <cuda_bf16.h>
#include <cstdint>
#include <math.h>

// Problem constants (fixed by the dataset)
#define NMAX 50000
#define EMAX 400000
#define ETMAX (NMAX + EMAX)   // edges + self loops
#define HEADS 4
#define HID 128

// ---------------- static scratch (no allocations allowed) ----------------
__device__ __align__(16) float g_Hbuf[(size_t)NMAX * 512];   // GEMM output h (pre-aggregation)
__device__ __align__(16) float g_ACT [(size_t)NMAX * 512];   // aggregated + elu activations
__device__ __align__(16) float g_as[NMAX * HEADS];
__device__ __align__(16) float g_ad[NMAX * HEADS];
__device__ __align__(16) float g_w [(size_t)ETMAX * HEADS];  // per-edge-per-head softmax weights
__device__ __align__(16) __nv_bfloat16 g_Whi[512 * 512];     // pre-split, transposed weights [n][k]
__device__ __align__(16) __nv_bfloat16 g_Wlo[512 * 512];
__device__ int g_deg[NMAX];
__device__ int g_incl[NMAX];
__device__ int g_bsum[64];
__device__ int g_boff[64];
__device__ int g_rowptr[NMAX + 1];
__device__ int g_col[ETMAX];
__device__ int g_widx[NMAX];

// ---------------- helpers ----------------
__device__ __forceinline__ uint32_t smem_u32(const void* p) {
    uint32_t a;
    asm("{ .reg .u64 t; cvta.to.shared.u64 t, %1; cvt.u32.u64 %0, t; }" : "=r"(a) : "l"(p));
    return a;
}
__device__ __forceinline__ void ldsm4(uint32_t& r0, uint32_t& r1, uint32_t& r2, uint32_t& r3, uint32_t addr) {
    asm volatile("ldmatrix.sync.aligned.m8n8.x4.shared.b16 {%0,%1,%2,%3}, [%4];"
                 : "=r"(r0), "=r"(r1), "=r"(r2), "=r"(r3) : "r"(addr));
}
__device__ __forceinline__ void ldsm2(uint32_t& r0, uint32_t& r1, uint32_t addr) {
    asm volatile("ldmatrix.sync.aligned.m8n8.x2.shared.b16 {%0,%1}, [%2];"
                 : "=r"(r0), "=r"(r1) : "r"(addr));
}
__device__ __forceinline__ void mma_bf16(float* c, const uint32_t* a, uint32_t b0, uint32_t b1) {
    asm volatile("mma.sync.aligned.m16n8k16.row.col.f32.bf16.bf16.f32 "
                 "{%0,%1,%2,%3}, {%4,%5,%6,%7}, {%8,%9}, {%0,%1,%2,%3};"
                 : "+f"(c[0]), "+f"(c[1]), "+f"(c[2]), "+f"(c[3])
                 : "r"(a[0]), "r"(a[1]), "r"(a[2]), "r"(a[3]), "r"(b0), "r"(b1));
}
__device__ __forceinline__ void cvt2(float a, float b, uint32_t& h, uint32_t& l) {
    __nv_bfloat16 ha = __float2bfloat16(a), hb = __float2bfloat16(b);
    float ra = a - __bfloat162float(ha), rb = b - __bfloat162float(hb);
    __nv_bfloat16 la = __float2bfloat16(ra), lb = __float2bfloat16(rb);
    h = (uint32_t)__bfloat16_as_ushort(ha) | ((uint32_t)__bfloat16_as_ushort(hb) << 16);
    l = (uint32_t)__bfloat16_as_ushort(la) | ((uint32_t)__bfloat16_as_ushort(lb) << 16);
}

// ---------------- CSR construction ----------------
__global__ void k_init_deg(int N) {
    int i = blockIdx.x * blockDim.x + threadIdx.x;
    if (i < N) g_deg[i] = 1;   // self-loop
}
__global__ void k_count(const int* __restrict__ dst, int E) {
    int i = blockIdx.x * blockDim.x + threadIdx.x;
    if (i < E) atomicAdd(&g_deg[dst[i]], 1);
}
__global__ void k_scan1(int N) {
    __shared__ int sh[1024];
    int i = blockIdx.x * 1024 + threadIdx.x;
    int v = (i < N) ? g_deg[i] : 0;
    sh[threadIdx.x] = v;
    __syncthreads();
    for (int off = 1; off < 1024; off <<= 1) {
        int u = (threadIdx.x >= off) ? sh[threadIdx.x - off] : 0;
        __syncthreads();
        sh[threadIdx.x] += u;
        __syncthreads();
    }
    if (i < N) g_incl[i] = sh[threadIdx.x];
    if (threadIdx.x == 1023) g_bsum[blockIdx.x] = sh[1023];
}
__global__ void k_scan2(int nb) {
    __shared__ int sh[64];
    int t = threadIdx.x;
    int v = (t < nb) ? g_bsum[t] : 0;
    sh[t] = v;
    __syncthreads();
    for (int off = 1; off < 64; off <<= 1) {
        int u = (t >= off) ? sh[t - off] : 0;
        __syncthreads();
        sh[t] += u;
        __syncthreads();
    }
    g_boff[t] = sh[t] - v;
}
__global__ void k_scan3(int N) {
    int i = blockIdx.x * blockDim.x + threadIdx.x;
    if (i < N) {
        g_rowptr[i + 1] = g_incl[i] + g_boff[i >> 10];
        if (i == 0) g_rowptr[0] = 0;
    }
}
__global__ void k_fill_self(int N) {
    int i = blockIdx.x * blockDim.x + threadIdx.x;
    if (i < N) { g_col[g_rowptr[i]] = i; g_widx[i] = 1; }
}
__global__ void k_fill_edges(const int* __restrict__ src, const int* __restrict__ dst, int E) {
    int i = blockIdx.x * blockDim.x + threadIdx.x;
    if (i < E) {
        int d = dst[i];
        int p = atomicAdd(&g_widx[d], 1);
        g_col[g_rowptr[d] + p] = src[i];
    }
}

// ---------------- weight split+transpose: Wt_hi/lo[n*K+k] from W[k*M+n] ----------------
__global__ void k_wsplit(const float* __restrict__ W, int K, int M) {
    int idx = blockIdx.x * blockDim.x + threadIdx.x;
    if (idx >= K * M) return;
    int n = idx / K, k = idx - n * K;
    float v = W[(size_t)k * M + n];
    __nv_bfloat16 h = __float2bfloat16(v);
    g_Whi[idx] = h;
    g_Wlo[idx] = __float2bfloat16(v - __bfloat162float(h));
}

// ---------------- HMMA split-bf16 GEMM: C[N,M] = A[N,K] @ W[K,M] ----------------
// 256 threads / 8 warps; block tile 128x128, BK=32; warp tile 64x32.
// Wh/Wl are pre-split bf16, transposed: [M][K] k-contiguous (B col-major for mma row.col).
#define APITCH 40   // bf16 per padded smem row (32 data + 8 pad = 80B)
__global__ void __launch_bounds__(256) k_gemm_mma(const float* __restrict__ A,
                                                  const __nv_bfloat16* __restrict__ Wh,
                                                  const __nv_bfloat16* __restrict__ Wl,
                                                  float* __restrict__ C,
                                                  int N, int K, int M) {
    __shared__ __align__(16) __nv_bfloat16 sAhi[128 * APITCH];
    __shared__ __align__(16) __nv_bfloat16 sAlo[128 * APITCH];
    __shared__ __align__(16) __nv_bfloat16 sBhi[128 * APITCH];
    __shared__ __align__(16) __nv_bfloat16 sBlo[128 * APITCH];

    int tid = threadIdx.x;
    int lane = tid & 31, wid = tid >> 5;
    int wm = wid >> 2, wn = wid & 3;           // warp grid 2x4
    int row0 = blockIdx.y * 128, col0 = blockIdx.x * 128;

    float acc[4][4][4];
#pragma unroll
    for (int i = 0; i < 4; i++)
#pragma unroll
        for (int j = 0; j < 4; j++)
#pragma unroll
            for (int q = 0; q < 4; q++) acc[i][j][q] = 0.f;

    // per-thread load indices: one half-row (16 elems) each
    int lrow = tid >> 1;          // 0..127
    int lhalf = tid & 1;          // 0/1 -> k offset 16
    int ar = row0 + lrow;
    const float* ap = A + (size_t)ar * K + lhalf * 16;
    const __nv_bfloat16* bph = Wh + (size_t)(col0 + lrow) * K + lhalf * 16;
    const __nv_bfloat16* bpl = Wl + (size_t)(col0 + lrow) * K + lhalf * 16;
    __nv_bfloat16* sa_h = sAhi + lrow * APITCH + lhalf * 16;
    __nv_bfloat16* sa_l = sAlo + lrow * APITCH + lhalf * 16;
    __nv_bfloat16* sb_h = sBhi + lrow * APITCH + lhalf * 16;
    __nv_bfloat16* sb_l = sBlo + lrow * APITCH + lhalf * 16;

    // ldmatrix smem addresses (per lane)
    uint32_t a_hi_base = smem_u32(sAhi), a_lo_base = smem_u32(sAlo);
    uint32_t b_hi_base = smem_u32(sBhi), b_lo_base = smem_u32(sBlo);
    int a_row = wm * 64 + (lane & 15);
    int a_kp = (lane >> 4) * 8;
    int b_row = wn * 32 + (lane & 7);
    int b_kp = ((lane >> 3) & 1) * 8;

    for (int k0 = 0; k0 < K; k0 += 32) {
        // --- A: load 16 f32, split, store hi/lo bf16 ---
        uint32_t h[8], l[8];
        if (ar < N) {
            const float4* a4 = (const float4*)(ap + k0);
#pragma unroll
            for (int q = 0; q < 4; q++) {
                float4 f = a4[q];
                cvt2(f.x, f.y, h[2 * q], l[2 * q]);
                cvt2(f.z, f.w, h[2 * q + 1], l[2 * q + 1]);
            }
        } else {
#pragma unroll
            for (int q = 0; q < 8; q++) { h[q] = 0; l[q] = 0; }
        }
        ((uint4*)sa_h)[0] = make_uint4(h[0], h[1], h[2], h[3]);
        ((uint4*)sa_h)[1] = make_uint4(h[4], h[5], h[6], h[7]);
        ((uint4*)sa_l)[0] = make_uint4(l[0], l[1], l[2], l[3]);
        ((uint4*)sa_l)[1] = make_uint4(l[4], l[5], l[6], l[7]);
        // --- B: copy pre-split bf16 ---
        const uint4* bh4 = (const uint4*)(bph + k0);
        const uint4* bl4 = (const uint4*)(bpl + k0);
        ((uint4*)sb_h)[0] = bh4[0];
        ((uint4*)sb_h)[1] = bh4[1];
        ((uint4*)sb_l)[0] = bl4[0];
        ((uint4*)sb_l)[1] = bl4[1];
        __syncthreads();

#pragma unroll
        for (int kk = 0; kk < 32; kk += 16) {
            uint32_t ahi[4][4], alo[4][4];
#pragma unroll
            for (int i = 0; i < 4; i++) {
                uint32_t off = ((a_row + i * 16) * APITCH + kk + a_kp) * 2;
                ldsm4(ahi[i][0], ahi[i][1], ahi[i][2], ahi[i][3], a_hi_base + off);
                ldsm4(alo[i][0], alo[i][1], alo[i][2], alo[i][3], a_lo_base + off);
            }
#pragma unroll
            for (int j = 0; j < 4; j++) {
                uint32_t boff = ((b_row + j * 8) * APITCH + kk + b_kp) * 2;
                uint32_t bh0, bh1, bl0, bl1;
                ldsm2(bh0, bh1, b_hi_base + boff);
                ldsm2(bl0, bl1, b_lo_base + boff);
#pragma unroll
                for (int i = 0; i < 4; i++) {
                    mma_bf16(acc[i][j], ahi[i], bh0, bh1);
                    mma_bf16(acc[i][j], ahi[i], bl0, bl1);
                    mma_bf16(acc[i][j], alo[i], bh0, bh1);
                }
            }
        }
        __syncthreads();
    }

    // --- epilogue ---
    int crow = row0 + wm * 64 + (lane >> 2);
    int ccol = col0 + wn * 32 + (lane & 3) * 2;
#pragma unroll
    for (int i = 0; i < 4; i++) {
        int r1 = crow + i * 16, r2 = r1 + 8;
#pragma unroll
        for (int j = 0; j < 4; j++) {
            int cc = ccol + j * 8;
            if (r1 < N) *(float2*)(C + (size_t)r1 * M + cc) = make_float2(acc[i][j][0], acc[i][j][1]);
            if (r2 < N) *(float2*)(C + (size_t)r2 * M + cc) = make_float2(acc[i][j][2], acc[i][j][3]);
        }
    }
}

// ---------------- per-(node,head) attention scalars ----------------
template <int H>
__global__ void k_alpha(const float* __restrict__ h,
                        const float* __restrict__ a_src,
                        const float* __restrict__ a_dst, int N) {
    int w = blockIdx.x * (blockDim.x >> 5) + (threadIdx.x >> 5);
    int lane = threadIdx.x & 31;
    if (w >= N * H) return;
    int n = w / H, hd = w % H;
    const float* row = h + (size_t)n * (H * HID) + hd * HID;
    float s1 = 0.f, s2 = 0.f;
#pragma unroll
    for (int c = lane; c < HID; c += 32) {
        float v = row[c];
        s1 = fmaf(v, a_src[hd * HID + c], s1);
        s2 = fmaf(v, a_dst[hd * HID + c], s2);
    }
    for (int off = 16; off; off >>= 1) {
        s1 += __shfl_xor_sync(0xffffffffu, s1, off);
        s2 += __shfl_xor_sync(0xffffffffu, s2, off);
    }
    if (lane == 0) { g_as[w] = s1; g_ad[w] = s2; }
}

// ---------------- per-node segment softmax over incoming edges ----------------
template <int H>
__global__ void k_softmax(int N) {
    int n = blockIdx.x * (blockDim.x >> 5) + (threadIdx.x >> 5);
    int lane = threadIdx.x & 31;
    if (n >= N) return;
    int beg = g_rowptr[n], end = g_rowptr[n + 1];
    float adh[H], mx[H], sm[H];
#pragma unroll
    for (int h = 0; h < H; h++) {
        adh[h] = g_ad[n * H + h];
        mx[h] = -1e30f;
        sm[h] = 0.f;
    }
    for (int j = beg + lane; j < end; j += 32) {
        int s = g_col[j];
#pragma unroll
        for (int h = 0; h < H; h++) {
            float e = g_as[s * H + h] + adh[h];
            e = e > 0.f ? e : 0.2f * e;           // leaky relu
            g_w[(size_t)j * H + h] = e;
            mx[h] = fmaxf(mx[h], e);
        }
    }
#pragma unroll
    for (int h = 0; h < H; h++)
        for (int off = 16; off; off >>= 1)
            mx[h] = fmaxf(mx[h], __shfl_xor_sync(0xffffffffu, mx[h], off));
    for (int j = beg + lane; j < end; j += 32) {
#pragma unroll
        for (int h = 0; h < H; h++) {
            float ex = __expf(g_w[(size_t)j * H + h] - mx[h]);
            g_w[(size_t)j * H + h] = ex;
            sm[h] += ex;
        }
    }
#pragma unroll
    for (int h = 0; h < H; h++) {
        for (int off = 16; off; off >>= 1)
            sm[h] += __shfl_xor_sync(0xffffffffu, sm[h], off);
        sm[h] = 1.f / sm[h];
    }
    for (int j = beg + lane; j < end; j += 32) {
#pragma unroll
        for (int h = 0; h < H; h++) g_w[(size_t)j * H + h] *= sm[h];
    }
}

// ---------------- per-node weighted gather-aggregate + bias + elu ----------------
template <int H>
__global__ __launch_bounds__(128) void k_aggregate(const float* __restrict__ hbuf,
                                                   const float* __restrict__ bias,
                                                   float* __restrict__ out, int N) {
    int n = blockIdx.x;
    if (n >= N) return;
    int t = threadIdx.x;   // 128
    float acc[H];
#pragma unroll
    for (int k = 0; k < H; k++) acc[k] = 0.f;
    int beg = g_rowptr[n], end = g_rowptr[n + 1];
    for (int j = beg; j < end; j++) {
        int s = g_col[j];
        const float* hr = hbuf + (size_t)s * (H * HID);
        if (H == 4) {
            float4 w4 = *(const float4*)(g_w + (size_t)j * 4);
            acc[0] = fmaf(w4.x, hr[t], acc[0]);
            acc[1] = fmaf(w4.y, hr[t + 128], acc[1]);
            acc[2] = fmaf(w4.z, hr[t + 256], acc[2]);
            acc[3] = fmaf(w4.w, hr[t + 384], acc[3]);
        } else {
            float ww = g_w[j];
            acc[0] = fmaf(ww, hr[t], acc[0]);
        }
    }
#pragma unroll
    for (int k = 0; k < H; k++) {
        int c = t + 128 * k;
        float v = acc[k] + bias[c];
        out[(size_t)n * (H * HID) + c] = v > 0.f ? v : (__expf(v) - 1.f);   // elu
    }
}

// ---------------- fc head ----------------
__global__ __launch_bounds__(64) void k_fc(const float* __restrict__ act,
                                           const float* __restrict__ w1,
                                           const float* __restrict__ b1,
                                           const float* __restrict__ w2,
                                           const float* __restrict__ b2,
                                           float* __restrict__ out, int N) {
    __shared__ float xs[128];
    __shared__ float part[2];
    int n = blockIdx.x;
    int t = threadIdx.x;   // 64
    xs[t]      = act[(size_t)n * 128 + t];
    xs[t + 64] = act[(size_t)n * 128 + t + 64];
    __syncthreads();
    float d = b1[t];
#pragma unroll 8
    for (int k = 0; k < 128; k++) d = fmaf(xs[k], w1[k * 64 + t], d);
    d = fmaxf(d, 0.f);
    float p = d * w2[t];
    for (int off = 16; off; off >>= 1) p += __shfl_xor_sync(0xffffffffu, p, off);
    if ((t & 31) == 0) part[t >> 5] = p;
    __syncthreads();
    if (t == 0) out[n] = 1.f / (1.f + __expf(-(part[0] + part[1] + b2[0])));
}

// ---------------- launch ----------------
extern "C" void kernel_launch(void* const* d_in, const int* in_sizes, int n_in,
                              void* d_out, int out_size) {
    const float* x      = (const float*)d_in[0];
    const int*   eidx   = (const int*)d_in[1];
    const float* W1     = (const float*)d_in[2];
    const float* a_src1 = (const float*)d_in[3];
    const float* a_dst1 = (const float*)d_in[4];
    const float* b1     = (const float*)d_in[5];
    const float* W2     = (const float*)d_in[6];
    const float* a_src2 = (const float*)d_in[7];
    const float* a_dst2 = (const float*)d_in[8];
    const float* b2     = (const float*)d_in[9];
    const float* W3     = (const float*)d_in[10];
    const float* a_src3 = (const float*)d_in[11];
    const float* a_dst3 = (const float*)d_in[12];
    const float* b3     = (const float*)d_in[13];
    const float* fc1w   = (const float*)d_in[14];
    const float* fc1b   = (const float*)d_in[15];
    const float* fc2w   = (const float*)d_in[16];
    const float* fc2b   = (const float*)d_in[17];
    float* out = (float*)d_out;

    int N = in_sizes[0] / 64;
    int E = in_sizes[1] / 2;
    const int* srcp = eidx;
    const int* dstp = eidx + E;

    float *Hb, *ACT;
    __nv_bfloat16 *Whi, *Wlo;
    cudaGetSymbolAddress((void**)&Hb, g_Hbuf);
    cudaGetSymbolAddress((void**)&ACT, g_ACT);
    cudaGetSymbolAddress((void**)&Whi, g_Whi);
    cudaGetSymbolAddress((void**)&Wlo, g_Wlo);

    int nb = (N + 1023) / 1024;
    int rowT = (N + 127) / 128;

    // CSR (dst-indexed) with self-loops
    k_init_deg<<<(N + 255) / 256, 256>>>(N);
    k_count<<<(E + 255) / 256, 256>>>(dstp, E);
    k_scan1<<<nb, 1024>>>(N);
    k_scan2<<<1, 64>>>(nb);
    k_scan3<<<(N + 255) / 256, 256>>>(N);
    k_fill_self<<<(N + 255) / 256, 256>>>(N);
    k_fill_edges<<<(E + 255) / 256, 256>>>(srcp, dstp, E);

    // Layer 1: h = x @ W1  [N,512], K=64
    k_wsplit<<<(64 * 512 + 255) / 256, 256>>>(W1, 64, 512);
    k_gemm_mma<<<dim3(4, rowT), 256>>>(x, Whi, Wlo, Hb, N, 64, 512);
    k_alpha<4><<<(N * 4 + 7) / 8, 256>>>(Hb, a_src1, a_dst1, N);
    k_softmax<4><<<(N + 7) / 8, 256>>>(N);
    k_aggregate<4><<<N, 128>>>(Hb, b1, ACT, N);

    // Layer 2: K=512, M=512
    k_wsplit<<<(512 * 512 + 255) / 256, 256>>>(W2, 512, 512);
    k_gemm_mma<<<dim3(4, rowT), 256>>>(ACT, Whi, Wlo, Hb, N, 512, 512);
    k_alpha<4><<<(N * 4 + 7) / 8, 256>>>(Hb, a_src2, a_dst2, N);
    k_softmax<4><<<(N + 7) / 8, 256>>>(N);
    k_aggregate<4><<<N, 128>>>(Hb, b2, ACT, N);

    // Layer 3: K=512, M=128 (heads=1)
    k_wsplit<<<(512 * 128 + 255) / 256, 256>>>(W3, 512, 128);
    k_gemm_mma<<<dim3(1, rowT), 256>>>(ACT, Whi, Wlo, Hb, N, 512, 128);
    k_alpha<1><<<(N + 7) / 8, 256>>>(Hb, a_src3, a_dst3, N);
    k_softmax<1><<<(N + 7) / 8, 256>>>(N);
    k_aggregate<1><<<N, 128>>>(Hb, b3, ACT, N);

    // MLP head
    k_fc<<<N, 64>>>(ACT, fc1w, fc1b, fc2w, fc2b, out, N);
}

// round 4
// speedup vs baseline: 1.6843x; 1.1492x over previous
#include <cuda_runtime.h>
#include <cuda_bf16.h>
#include <cstdint>
#include <math.h>

// Problem constants (fixed by the dataset)
#define NMAX 50000
#define EMAX 400000
#define ETMAX (NMAX + EMAX)   // edges + self loops
#define HEADS 4
#define HID 128

// ---------------- static scratch (no allocations allowed) ----------------
__device__ __align__(16) float g_Hbuf[(size_t)NMAX * 512];        // GEMM output h (pre-aggregation)
__device__ __align__(16) __nv_bfloat16 g_Ahi[(size_t)NMAX * 512]; // split activations (GEMM A operand)
__device__ __align__(16) __nv_bfloat16 g_Alo[(size_t)NMAX * 512];
__device__ __align__(16) float g_as[NMAX * HEADS];
__device__ __align__(16) float g_ad[NMAX * HEADS];
__device__ __align__(16) float g_w [(size_t)ETMAX * HEADS];       // per-edge-per-head softmax weights
__device__ __align__(16) __nv_bfloat16 g_Whi[512 * 512];          // pre-split, transposed weights [n][k]
__device__ __align__(16) __nv_bfloat16 g_Wlo[512 * 512];
__device__ int g_deg[NMAX];
__device__ int g_incl[NMAX];
__device__ int g_bsum[64];
__device__ int g_boff[64];
__device__ int g_rowptr[NMAX + 1];
__device__ int g_col[ETMAX];
__device__ int g_widx[NMAX];

// ---------------- helpers ----------------
__device__ __forceinline__ uint32_t smem_u32(const void* p) {
    uint32_t a;
    asm("{ .reg .u64 t; cvta.to.shared.u64 t, %1; cvt.u32.u64 %0, t; }" : "=r"(a) : "l"(p));
    return a;
}
__device__ __forceinline__ void ldsm4(uint32_t& r0, uint32_t& r1, uint32_t& r2, uint32_t& r3, uint32_t addr) {
    asm volatile("ldmatrix.sync.aligned.m8n8.x4.shared.b16 {%0,%1,%2,%3}, [%4];"
                 : "=r"(r0), "=r"(r1), "=r"(r2), "=r"(r3) : "r"(addr));
}
__device__ __forceinline__ void ldsm2(uint32_t& r0, uint32_t& r1, uint32_t addr) {
    asm volatile("ldmatrix.sync.aligned.m8n8.x2.shared.b16 {%0,%1}, [%2];"
                 : "=r"(r0), "=r"(r1) : "r"(addr));
}
__device__ __forceinline__ void mma_bf16(float* c, const uint32_t* a, uint32_t b0, uint32_t b1) {
    asm volatile("mma.sync.aligned.m16n8k16.row.col.f32.bf16.bf16.f32 "
                 "{%0,%1,%2,%3}, {%4,%5,%6,%7}, {%8,%9}, {%0,%1,%2,%3};"
                 : "+f"(c[0]), "+f"(c[1]), "+f"(c[2]), "+f"(c[3])
                 : "r"(a[0]), "r"(a[1]), "r"(a[2]), "r"(a[3]), "r"(b0), "r"(b1));
}
__device__ __forceinline__ void cp_async16(uint32_t dst, const void* src, int sbytes) {
    asm volatile("cp.async.cg.shared.global [%0], [%1], 16, %2;"
                 :: "r"(dst), "l"(src), "r"(sbytes) : "memory");
}
__device__ __forceinline__ void cp_commit() { asm volatile("cp.async.commit_group;" ::: "memory"); }
__device__ __forceinline__ void cp_wait1() { asm volatile("cp.async.wait_group 1;" ::: "memory"); }
__device__ __forceinline__ void cp_wait0() { asm volatile("cp.async.wait_group 0;" ::: "memory"); }

// ---------------- CSR construction ----------------
__global__ void k_init_deg(int N) {
    int i = blockIdx.x * blockDim.x + threadIdx.x;
    if (i < N) g_deg[i] = 1;   // self-loop
}
__global__ void k_count(const int* __restrict__ dst, int E) {
    int i = blockIdx.x * blockDim.x + threadIdx.x;
    if (i < E) atomicAdd(&g_deg[dst[i]], 1);
}
__global__ void k_scan1(int N) {
    __shared__ int sh[1024];
    int i = blockIdx.x * 1024 + threadIdx.x;
    int v = (i < N) ? g_deg[i] : 0;
    sh[threadIdx.x] = v;
    __syncthreads();
    for (int off = 1; off < 1024; off <<= 1) {
        int u = (threadIdx.x >= off) ? sh[threadIdx.x - off] : 0;
        __syncthreads();
        sh[threadIdx.x] += u;
        __syncthreads();
    }
    if (i < N) g_incl[i] = sh[threadIdx.x];
    if (threadIdx.x == 1023) g_bsum[blockIdx.x] = sh[1023];
}
__global__ void k_scan2(int nb) {
    __shared__ int sh[64];
    int t = threadIdx.x;
    int v = (t < nb) ? g_bsum[t] : 0;
    sh[t] = v;
    __syncthreads();
    for (int off = 1; off < 64; off <<= 1) {
        int u = (t >= off) ? sh[t - off] : 0;
        __syncthreads();
        sh[t] += u;
        __syncthreads();
    }
    g_boff[t] = sh[t] - v;
}
__global__ void k_scan3(int N) {
    int i = blockIdx.x * blockDim.x + threadIdx.x;
    if (i < N) {
        g_rowptr[i + 1] = g_incl[i] + g_boff[i >> 10];
        if (i == 0) g_rowptr[0] = 0;
    }
}
__global__ void k_fill_self(int N) {
    int i = blockIdx.x * blockDim.x + threadIdx.x;
    if (i < N) { g_col[g_rowptr[i]] = i; g_widx[i] = 1; }
}
__global__ void k_fill_edges(const int* __restrict__ src, const int* __restrict__ dst, int E) {
    int i = blockIdx.x * blockDim.x + threadIdx.x;
    if (i < E) {
        int d = dst[i];
        int p = atomicAdd(&g_widx[d], 1);
        g_col[g_rowptr[d] + p] = src[i];
    }
}

// ---------------- weight split+transpose: Wt_hi/lo[n*K+k] from W[k*M+n] ----------------
__global__ void k_wsplit(const float* __restrict__ W, int K, int M) {
    int idx = blockIdx.x * blockDim.x + threadIdx.x;
    if (idx >= K * M) return;
    int n = idx / K, k = idx - n * K;
    float v = W[(size_t)k * M + n];
    __nv_bfloat16 h = __float2bfloat16(v);
    g_Whi[idx] = h;
    g_Wlo[idx] = __float2bfloat16(v - __bfloat162float(h));
}

// ---------------- activation split (for layer-1 input x) ----------------
__global__ void k_asplit(const float* __restrict__ X, int total) {
    int i = blockIdx.x * blockDim.x + threadIdx.x;
    if (i >= total) return;
    float v = X[i];
    __nv_bfloat16 h = __float2bfloat16(v);
    g_Ahi[i] = h;
    g_Alo[i] = __float2bfloat16(v - __bfloat162float(h));
}

// ---------------- HMMA split-bf16 GEMM: C[N,M] = (Ahi+Alo)[N,K] @ W[K,M] ----------------
// 256 threads / 8 warps; block tile 128x128, BK=32; warp tile 64x32.
// cp.async double-buffered. All operands pre-split bf16; W transposed [M][K].
#define PITCHB 80          // bytes per padded smem row (64 data + 16 pad)
#define BUFSZ  (128 * PITCHB)   // 10240 B per buffer
#define STAGESZ (4 * BUFSZ)     // AHI, ALO, BHI, BLO
__global__ void __launch_bounds__(256) k_gemm_mma(const __nv_bfloat16* __restrict__ Ah,
                                                  const __nv_bfloat16* __restrict__ Al,
                                                  const __nv_bfloat16* __restrict__ Wh,
                                                  const __nv_bfloat16* __restrict__ Wl,
                                                  float* __restrict__ C,
                                                  int N, int K, int M) {
    extern __shared__ char smem[];
    uint32_t sb = smem_u32(smem);

    int tid = threadIdx.x;
    int lane = tid & 31, wid = tid >> 5;
    int wm = wid >> 2, wn = wid & 3;           // warp grid 2x4
    int row0 = blockIdx.y * 128, col0 = blockIdx.x * 128;

    float acc[4][4][4];
#pragma unroll
    for (int i = 0; i < 4; i++)
#pragma unroll
        for (int j = 0; j < 4; j++)
#pragma unroll
            for (int q = 0; q < 4; q++) acc[i][j][q] = 0.f;

    // per-thread cp.async chunks: 2 chunks (16B) per buffer
    int c0row = tid >> 1, c0col = (tid & 1) * 2;    // chunk = tid*2+b -> row=chunk>>2, c=chunk&3
    // chunk layout: chunks tid*2, tid*2+1 -> rows tid>>1 (both), cols (tid&1)*2, (tid&1)*2+1
    int arow_g = row0 + c0row;
    int brow_g = col0 + c0row;
    const __nv_bfloat16* aph = Ah + (size_t)arow_g * K + c0col * 8;
    const __nv_bfloat16* apl = Al + (size_t)arow_g * K + c0col * 8;
    const __nv_bfloat16* bph = Wh + (size_t)brow_g * K + c0col * 8;
    const __nv_bfloat16* bpl = Wl + (size_t)brow_g * K + c0col * 8;
    int avalid = (arow_g < N) ? 16 : 0;
    uint32_t dbase = sb + c0row * PITCHB + c0col * 16;

    // ldmatrix lane addressing
    int a_row = wm * 64 + (lane & 15);
    int a_kp = (lane >> 4) * 8;
    int b_row = wn * 32 + (lane & 7);
    int b_kp = ((lane >> 3) & 1) * 8;

    int nch = K >> 5;

    // prologue: stage 0
    {
#pragma unroll
        for (int b = 0; b < 2; b++) {
            uint32_t d = dbase + b * 16;
            cp_async16(d,              aph + b * 8, avalid);
            cp_async16(d + BUFSZ,      apl + b * 8, avalid);
            cp_async16(d + 2 * BUFSZ,  bph + b * 8, 16);
            cp_async16(d + 3 * BUFSZ,  bpl + b * 8, 16);
        }
        cp_commit();
    }

    for (int ch = 0; ch < nch; ch++) {
        if (ch + 1 < nch) {
            int koff = (ch + 1) * 32;
            uint32_t sdst = dbase + ((ch + 1) & 1) * STAGESZ;
#pragma unroll
            for (int b = 0; b < 2; b++) {
                uint32_t d = sdst + b * 16;
                cp_async16(d,              aph + koff + b * 8, avalid);
                cp_async16(d + BUFSZ,      apl + koff + b * 8, avalid);
                cp_async16(d + 2 * BUFSZ,  bph + koff + b * 8, 16);
                cp_async16(d + 3 * BUFSZ,  bpl + koff + b * 8, 16);
            }
            cp_commit();
            cp_wait1();
        } else {
            cp_wait0();
        }
        __syncthreads();

        uint32_t st = sb + (ch & 1) * STAGESZ;
#pragma unroll
        for (int kk = 0; kk < 32; kk += 16) {
            uint32_t ahi[4][4], alo[4][4];
#pragma unroll
            for (int i = 0; i < 4; i++) {
                uint32_t off = (a_row + i * 16) * PITCHB + (kk + a_kp) * 2;
                ldsm4(ahi[i][0], ahi[i][1], ahi[i][2], ahi[i][3], st + off);
                ldsm4(alo[i][0], alo[i][1], alo[i][2], alo[i][3], st + BUFSZ + off);
            }
#pragma unroll
            for (int j = 0; j < 4; j++) {
                uint32_t boff = (b_row + j * 8) * PITCHB + (kk + b_kp) * 2;
                uint32_t bh0, bh1, bl0, bl1;
                ldsm2(bh0, bh1, st + 2 * BUFSZ + boff);
                ldsm2(bl0, bl1, st + 3 * BUFSZ + boff);
#pragma unroll
                for (int i = 0; i < 4; i++) {
                    mma_bf16(acc[i][j], ahi[i], bh0, bh1);
                    mma_bf16(acc[i][j], ahi[i], bl0, bl1);
                    mma_bf16(acc[i][j], alo[i], bh0, bh1);
                }
            }
        }
        __syncthreads();
    }

    // --- epilogue ---
    int crow = row0 + wm * 64 + (lane >> 2);
    int ccol = col0 + wn * 32 + (lane & 3) * 2;
#pragma unroll
    for (int i = 0; i < 4; i++) {
        int r1 = crow + i * 16, r2 = r1 + 8;
#pragma unroll
        for (int j = 0; j < 4; j++) {
            int cc = ccol + j * 8;
            if (r1 < N) *(float2*)(C + (size_t)r1 * M + cc) = make_float2(acc[i][j][0], acc[i][j][1]);
            if (r2 < N) *(float2*)(C + (size_t)r2 * M + cc) = make_float2(acc[i][j][2], acc[i][j][3]);
        }
    }
}

// ---------------- per-(node,head) attention scalars ----------------
template <int H>
__global__ void k_alpha(const float* __restrict__ h,
                        const float* __restrict__ a_src,
                        const float* __restrict__ a_dst, int N) {
    int w = blockIdx.x * (blockDim.x >> 5) + (threadIdx.x >> 5);
    int lane = threadIdx.x & 31;
    if (w >= N * H) return;
    int n = w / H, hd = w % H;
    const float* row = h + (size_t)n * (H * HID) + hd * HID;
    float s1 = 0.f, s2 = 0.f;
#pragma unroll
    for (int c = lane; c < HID; c += 32) {
        float v = row[c];
        s1 = fmaf(v, a_src[hd * HID + c], s1);
        s2 = fmaf(v, a_dst[hd * HID + c], s2);
    }
    for (int off = 16; off; off >>= 1) {
        s1 += __shfl_xor_sync(0xffffffffu, s1, off);
        s2 += __shfl_xor_sync(0xffffffffu, s2, off);
    }
    if (lane == 0) { g_as[w] = s1; g_ad[w] = s2; }
}

// ---------------- per-node segment softmax over incoming edges ----------------
template <int H>
__global__ void k_softmax(int N) {
    int n = blockIdx.x * (blockDim.x >> 5) + (threadIdx.x >> 5);
    int lane = threadIdx.x & 31;
    if (n >= N) return;
    int beg = g_rowptr[n], end = g_rowptr[n + 1];
    float adh[H], mx[H], sm[H];
#pragma unroll
    for (int h = 0; h < H; h++) {
        adh[h] = g_ad[n * H + h];
        mx[h] = -1e30f;
        sm[h] = 0.f;
    }
    for (int j = beg + lane; j < end; j += 32) {
        int s = g_col[j];
#pragma unroll
        for (int h = 0; h < H; h++) {
            float e = g_as[s * H + h] + adh[h];
            e = e > 0.f ? e : 0.2f * e;           // leaky relu
            g_w[(size_t)j * H + h] = e;
            mx[h] = fmaxf(mx[h], e);
        }
    }
#pragma unroll
    for (int h = 0; h < H; h++)
        for (int off = 16; off; off >>= 1)
            mx[h] = fmaxf(mx[h], __shfl_xor_sync(0xffffffffu, mx[h], off));
    for (int j = beg + lane; j < end; j += 32) {
#pragma unroll
        for (int h = 0; h < H; h++) {
            float ex = __expf(g_w[(size_t)j * H + h] - mx[h]);
            g_w[(size_t)j * H + h] = ex;
            sm[h] += ex;
        }
    }
#pragma unroll
    for (int h = 0; h < H; h++) {
        for (int off = 16; off; off >>= 1)
            sm[h] += __shfl_xor_sync(0xffffffffu, sm[h], off);
        sm[h] = 1.f / sm[h];
    }
    for (int j = beg + lane; j < end; j += 32) {
#pragma unroll
        for (int h = 0; h < H; h++) g_w[(size_t)j * H + h] *= sm[h];
    }
}

// ---------------- per-node weighted gather-aggregate + bias + elu -> split bf16 ----------------
template <int H>
__global__ __launch_bounds__(128) void k_aggregate(const float* __restrict__ hbuf,
                                                   const float* __restrict__ bias,
                                                   int N) {
    int n = blockIdx.x;
    if (n >= N) return;
    int t = threadIdx.x;   // 128
    float acc[H];
#pragma unroll
    for (int k = 0; k < H; k++) acc[k] = 0.f;
    int beg = g_rowptr[n], end = g_rowptr[n + 1];
    for (int j = beg; j < end; j++) {
        int s = g_col[j];
        const float* hr = hbuf + (size_t)s * (H * HID);
        if (H == 4) {
            float4 w4 = *(const float4*)(g_w + (size_t)j * 4);
            acc[0] = fmaf(w4.x, hr[t], acc[0]);
            acc[1] = fmaf(w4.y, hr[t + 128], acc[1]);
            acc[2] = fmaf(w4.z, hr[t + 256], acc[2]);
            acc[3] = fmaf(w4.w, hr[t + 384], acc[3]);
        } else {
            float ww = g_w[j];
            acc[0] = fmaf(ww, hr[t], acc[0]);
        }
    }
#pragma unroll
    for (int k = 0; k < H; k++) {
        int c = t + 128 * k;
        float v = acc[k] + bias[c];
        v = v > 0.f ? v : (__expf(v) - 1.f);   // elu
        __nv_bfloat16 hv = __float2bfloat16(v);
        size_t o = (size_t)n * (H * HID) + c;
        g_Ahi[o] = hv;
        g_Alo[o] = __float2bfloat16(v - __bfloat162float(hv));
    }
}

// ---------------- fc head (reads split bf16 activations) ----------------
__global__ __launch_bounds__(64) void k_fc(const float* __restrict__ w1,
                                           const float* __restrict__ b1,
                                           const float* __restrict__ w2,
                                           const float* __restrict__ b2,
                                           float* __restrict__ out, int N) {
    __shared__ float xs[128];
    __shared__ float part[2];
    int n = blockIdx.x;
    int t = threadIdx.x;   // 64
    size_t base = (size_t)n * 128;
    xs[t]      = __bfloat162float(g_Ahi[base + t])      + __bfloat162float(g_Alo[base + t]);
    xs[t + 64] = __bfloat162float(g_Ahi[base + t + 64]) + __bfloat162float(g_Alo[base + t + 64]);
    __syncthreads();
    float d = b1[t];
#pragma unroll 8
    for (int k = 0; k < 128; k++) d = fmaf(xs[k], w1[k * 64 + t], d);
    d = fmaxf(d, 0.f);
    float p = d * w2[t];
    for (int off = 16; off; off >>= 1) p += __shfl_xor_sync(0xffffffffu, p, off);
    if ((t & 31) == 0) part[t >> 5] = p;
    __syncthreads();
    if (t == 0) out[n] = 1.f / (1.f + __expf(-(part[0] + part[1] + b2[0])));
}

// ---------------- launch ----------------
extern "C" void kernel_launch(void* const* d_in, const int* in_sizes, int n_in,
                              void* d_out, int out_size) {
    const float* x      = (const float*)d_in[0];
    const int*   eidx   = (const int*)d_in[1];
    const float* W1     = (const float*)d_in[2];
    const float* a_src1 = (const float*)d_in[3];
    const float* a_dst1 = (const float*)d_in[4];
    const float* b1     = (const float*)d_in[5];
    const float* W2     = (const float*)d_in[6];
    const float* a_src2 = (const float*)d_in[7];
    const float* a_dst2 = (const float*)d_in[8];
    const float* b2     = (const float*)d_in[9];
    const float* W3     = (const float*)d_in[10];
    const float* a_src3 = (const float*)d_in[11];
    const float* a_dst3 = (const float*)d_in[12];
    const float* b3     = (const float*)d_in[13];
    const float* fc1w   = (const float*)d_in[14];
    const float* fc1b   = (const float*)d_in[15];
    const float* fc2w   = (const float*)d_in[16];
    const float* fc2b   = (const float*)d_in[17];
    float* out = (float*)d_out;

    int N = in_sizes[0] / 64;
    int E = in_sizes[1] / 2;
    const int* srcp = eidx;
    const int* dstp = eidx + E;

    float* Hb;
    __nv_bfloat16 *Whi, *Wlo, *Ahi, *Alo;
    cudaGetSymbolAddress((void**)&Hb, g_Hbuf);
    cudaGetSymbolAddress((void**)&Whi, g_Whi);
    cudaGetSymbolAddress((void**)&Wlo, g_Wlo);
    cudaGetSymbolAddress((void**)&Ahi, g_Ahi);
    cudaGetSymbolAddress((void**)&Alo, g_Alo);

    const int GSMEM = 2 * STAGESZ;   // 81920
    static int s_attr_done = 0;
    if (!s_attr_done) {
        cudaFuncSetAttribute(k_gemm_mma, cudaFuncAttributeMaxDynamicSharedMemorySize, GSMEM);
        s_attr_done = 1;
    }

    int nb = (N + 1023) / 1024;
    int rowT = (N + 127) / 128;

    // CSR (dst-indexed) with self-loops
    k_init_deg<<<(N + 255) / 256, 256>>>(N);
    k_count<<<(E + 255) / 256, 256>>>(dstp, E);
    k_scan1<<<nb, 1024>>>(N);
    k_scan2<<<1, 64>>>(nb);
    k_scan3<<<(N + 255) / 256, 256>>>(N);
    k_fill_self<<<(N + 255) / 256, 256>>>(N);
    k_fill_edges<<<(E + 255) / 256, 256>>>(srcp, dstp, E);

    // Layer 1: h = x @ W1  [N,512], K=64
    k_asplit<<<(N * 64 + 255) / 256, 256>>>(x, N * 64);
    k_wsplit<<<(64 * 512 + 255) / 256, 256>>>(W1, 64, 512);
    k_gemm_mma<<<dim3(4, rowT), 256, GSMEM>>>(Ahi, Alo, Whi, Wlo, Hb, N, 64, 512);
    k_alpha<4><<<(N * 4 + 7) / 8, 256>>>(Hb, a_src1, a_dst1, N);
    k_softmax<4><<<(N + 7) / 8, 256>>>(N);
    k_aggregate<4><<<N, 128>>>(Hb, b1, N);

    // Layer 2: K=512, M=512
    k_wsplit<<<(512 * 512 + 255) / 256, 256>>>(W2, 512, 512);
    k_gemm_mma<<<dim3(4, rowT), 256, GSMEM>>>(Ahi, Alo, Whi, Wlo, Hb, N, 512, 512);
    k_alpha<4><<<(N * 4 + 7) / 8, 256>>>(Hb, a_src2, a_dst2, N);
    k_softmax<4><<<(N + 7) / 8, 256>>>(N);
    k_aggregate<4><<<N, 128>>>(Hb, b2, N);

    // Layer 3: K=512, M=128 (heads=1)
    k_wsplit<<<(512 * 128 + 255) / 256, 256>>>(W3, 512, 128);
    k_gemm_mma<<<dim3(1, rowT), 256, GSMEM>>>(Ahi, Alo, Whi, Wlo, Hb, N, 512, 128);
    k_alpha<1><<<(N + 7) / 8, 256>>>(Hb, a_src3, a_dst3, N);
    k_softmax<1><<<(N + 7) / 8, 256>>>(N);
    k_aggregate<1><<<N, 128>>>(Hb, b3, N);

    // MLP head
    k_fc<<<N, 64>>>(fc1w, fc1b, fc2w, fc2b, out, N);
}

// round 5
// speedup vs baseline: 1.8383x; 1.0914x over previous
#include <cuda_runtime.h>
#include <cuda_bf16.h>
#include <cstdint>
#include <math.h>

// Problem constants (fixed by the dataset)
#define NMAX 50000
#define EMAX 400000
#define ETMAX (NMAX + EMAX)   // edges + self loops
#define HEADS 4
#define HID 128

// ---------------- static scratch (no allocations allowed) ----------------
__device__ __align__(16) float g_Hbuf[(size_t)NMAX * 512];        // GEMM output h (pre-aggregation)
__device__ __align__(16) __nv_bfloat16 g_Ahi[(size_t)NMAX * 512]; // split activations (GEMM A operand)
__device__ __align__(16) __nv_bfloat16 g_Alo[(size_t)NMAX * 512];
__device__ __align__(16) float g_as[NMAX * HEADS];
__device__ __align__(16) float g_ad[NMAX * HEADS];
__device__ __align__(16) float g_w [(size_t)ETMAX * HEADS];       // per-edge-per-head softmax weights
__device__ __align__(16) __nv_bfloat16 g_Whi[512 * 512];          // pre-split, transposed weights [n][k]
__device__ __align__(16) __nv_bfloat16 g_Wlo[512 * 512];
__device__ int g_deg[NMAX];
__device__ int g_incl[NMAX];
__device__ int g_bsum[64];
__device__ int g_boff[64];
__device__ int g_rowptr[NMAX + 1];
__device__ int g_col[ETMAX];
__device__ int g_widx[NMAX];

// ---------------- helpers ----------------
__device__ __forceinline__ uint32_t smem_u32(const void* p) {
    uint32_t a;
    asm("{ .reg .u64 t; cvta.to.shared.u64 t, %1; cvt.u32.u64 %0, t; }" : "=r"(a) : "l"(p));
    return a;
}
__device__ __forceinline__ void ldsm4(uint32_t& r0, uint32_t& r1, uint32_t& r2, uint32_t& r3, uint32_t addr) {
    asm volatile("ldmatrix.sync.aligned.m8n8.x4.shared.b16 {%0,%1,%2,%3}, [%4];"
                 : "=r"(r0), "=r"(r1), "=r"(r2), "=r"(r3) : "r"(addr));
}
__device__ __forceinline__ void ldsm2(uint32_t& r0, uint32_t& r1, uint32_t addr) {
    asm volatile("ldmatrix.sync.aligned.m8n8.x2.shared.b16 {%0,%1}, [%2];"
                 : "=r"(r0), "=r"(r1) : "r"(addr));
}
__device__ __forceinline__ void mma_bf16(float* c, const uint32_t* a, uint32_t b0, uint32_t b1) {
    asm volatile("mma.sync.aligned.m16n8k16.row.col.f32.bf16.bf16.f32 "
                 "{%0,%1,%2,%3}, {%4,%5,%6,%7}, {%8,%9}, {%0,%1,%2,%3};"
                 : "+f"(c[0]), "+f"(c[1]), "+f"(c[2]), "+f"(c[3])
                 : "r"(a[0]), "r"(a[1]), "r"(a[2]), "r"(a[3]), "r"(b0), "r"(b1));
}
__device__ __forceinline__ void cp_async16(uint32_t dst, const void* src, int sbytes) {
    asm volatile("cp.async.cg.shared.global [%0], [%1], 16, %2;"
                 :: "r"(dst), "l"(src), "r"(sbytes) : "memory");
}
__device__ __forceinline__ void cp_commit() { asm volatile("cp.async.commit_group;" ::: "memory"); }
__device__ __forceinline__ void cp_wait1() { asm volatile("cp.async.wait_group 1;" ::: "memory"); }
__device__ __forceinline__ void cp_wait0() { asm volatile("cp.async.wait_group 0;" ::: "memory"); }

// ---------------- CSR construction ----------------
__global__ void k_init_deg(int N) {
    int i = blockIdx.x * blockDim.x + threadIdx.x;
    if (i < N) g_deg[i] = 1;   // self-loop
}
__global__ void k_count(const int* __restrict__ dst, int E) {
    int i = blockIdx.x * blockDim.x + threadIdx.x;
    if (i < E) atomicAdd(&g_deg[dst[i]], 1);
}
__global__ void k_scan1(int N) {
    __shared__ int sh[1024];
    int i = blockIdx.x * 1024 + threadIdx.x;
    int v = (i < N) ? g_deg[i] : 0;
    sh[threadIdx.x] = v;
    __syncthreads();
    for (int off = 1; off < 1024; off <<= 1) {
        int u = (threadIdx.x >= off) ? sh[threadIdx.x - off] : 0;
        __syncthreads();
        sh[threadIdx.x] += u;
        __syncthreads();
    }
    if (i < N) g_incl[i] = sh[threadIdx.x];
    if (threadIdx.x == 1023) g_bsum[blockIdx.x] = sh[1023];
}
__global__ void k_scan2(int nb) {
    __shared__ int sh[64];
    int t = threadIdx.x;
    int v = (t < nb) ? g_bsum[t] : 0;
    sh[t] = v;
    __syncthreads();
    for (int off = 1; off < 64; off <<= 1) {
        int u = (t >= off) ? sh[t - off] : 0;
        __syncthreads();
        sh[t] += u;
        __syncthreads();
    }
    g_boff[t] = sh[t] - v;
}
__global__ void k_scan3(int N) {
    int i = blockIdx.x * blockDim.x + threadIdx.x;
    if (i < N) {
        g_rowptr[i + 1] = g_incl[i] + g_boff[i >> 10];
        if (i == 0) g_rowptr[0] = 0;
    }
}
__global__ void k_fill_self(int N) {
    int i = blockIdx.x * blockDim.x + threadIdx.x;
    if (i < N) { g_col[g_rowptr[i]] = i; g_widx[i] = 1; }
}
__global__ void k_fill_edges(const int* __restrict__ src, const int* __restrict__ dst, int E) {
    int i = blockIdx.x * blockDim.x + threadIdx.x;
    if (i < E) {
        int d = dst[i];
        int p = atomicAdd(&g_widx[d], 1);
        g_col[g_rowptr[d] + p] = src[i];
    }
}

// ---------------- weight split+transpose: Wt_hi/lo[n*K+k] from W[k*M+n] ----------------
__global__ void k_wsplit(const float* __restrict__ W, int K, int M) {
    int idx = blockIdx.x * blockDim.x + threadIdx.x;
    if (idx >= K * M) return;
    int n = idx / K, k = idx - n * K;
    float v = W[(size_t)k * M + n];
    __nv_bfloat16 h = __float2bfloat16(v);
    g_Whi[idx] = h;
    g_Wlo[idx] = __float2bfloat16(v - __bfloat162float(h));
}

// ---------------- activation split (for layer-1 input x) ----------------
__global__ void k_asplit(const float* __restrict__ X, int total) {
    int i = blockIdx.x * blockDim.x + threadIdx.x;
    if (i >= total) return;
    float v = X[i];
    __nv_bfloat16 h = __float2bfloat16(v);
    g_Ahi[i] = h;
    g_Alo[i] = __float2bfloat16(v - __bfloat162float(h));
}

// ---------------- HMMA split-bf16 GEMM with fused alpha epilogue ----------------
// C[N,M] = (Ahi+Alo)[N,K] @ W[K,M]; also g_as/g_ad += C_tile . a_src/a_dst (per head).
// Block tile 128x128, BK=32, 8 warps, cp.async double-buffered.
// Column tile == one head (tile width 128 == HID).
#define PITCHB 80          // bytes per padded smem row (64 data + 16 pad)
#define BUFSZ  (128 * PITCHB)   // 10240 B per buffer
#define STAGESZ (4 * BUFSZ)     // AHI, ALO, BHI, BLO
__global__ void __launch_bounds__(256) k_gemm_mma(const __nv_bfloat16* __restrict__ Ah,
                                                  const __nv_bfloat16* __restrict__ Al,
                                                  const __nv_bfloat16* __restrict__ Wh,
                                                  const __nv_bfloat16* __restrict__ Wl,
                                                  float* __restrict__ C,
                                                  const float* __restrict__ avec_s,
                                                  const float* __restrict__ avec_d,
                                                  int N, int K, int M, int H) {
    extern __shared__ char smem[];
    uint32_t sb = smem_u32(smem);

    int tid = threadIdx.x;
    int lane = tid & 31, wid = tid >> 5;
    int wm = wid >> 2, wn = wid & 3;           // warp grid 2x4
    int row0 = blockIdx.y * 128, col0 = blockIdx.x * 128;
    int hd = blockIdx.x;                        // head index (tile width == HID)

    float acc[4][4][4];
#pragma unroll
    for (int i = 0; i < 4; i++)
#pragma unroll
        for (int j = 0; j < 4; j++)
#pragma unroll
            for (int q = 0; q < 4; q++) acc[i][j][q] = 0.f;

    // per-thread cp.async chunks: 2 chunks (16B) per buffer
    int c0row = tid >> 1, c0col = (tid & 1) * 2;
    int arow_g = row0 + c0row;
    int brow_g = col0 + c0row;
    const __nv_bfloat16* aph = Ah + (size_t)arow_g * K + c0col * 8;
    const __nv_bfloat16* apl = Al + (size_t)arow_g * K + c0col * 8;
    const __nv_bfloat16* bph = Wh + (size_t)brow_g * K + c0col * 8;
    const __nv_bfloat16* bpl = Wl + (size_t)brow_g * K + c0col * 8;
    int avalid = (arow_g < N) ? 16 : 0;
    uint32_t dbase = sb + c0row * PITCHB + c0col * 16;

    // ldmatrix lane addressing
    int a_row = wm * 64 + (lane & 15);
    int a_kp = (lane >> 4) * 8;
    int b_row = wn * 32 + (lane & 7);
    int b_kp = ((lane >> 3) & 1) * 8;

    int nch = K >> 5;

    // prologue: stage 0
    {
#pragma unroll
        for (int b = 0; b < 2; b++) {
            uint32_t d = dbase + b * 16;
            cp_async16(d,              aph + b * 8, avalid);
            cp_async16(d + BUFSZ,      apl + b * 8, avalid);
            cp_async16(d + 2 * BUFSZ,  bph + b * 8, 16);
            cp_async16(d + 3 * BUFSZ,  bpl + b * 8, 16);
        }
        cp_commit();
    }

    for (int ch = 0; ch < nch; ch++) {
        if (ch + 1 < nch) {
            int koff = (ch + 1) * 32;
            uint32_t sdst = dbase + ((ch + 1) & 1) * STAGESZ;
#pragma unroll
            for (int b = 0; b < 2; b++) {
                uint32_t d = sdst + b * 16;
                cp_async16(d,              aph + koff + b * 8, avalid);
                cp_async16(d + BUFSZ,      apl + koff + b * 8, avalid);
                cp_async16(d + 2 * BUFSZ,  bph + koff + b * 8, 16);
                cp_async16(d + 3 * BUFSZ,  bpl + koff + b * 8, 16);
            }
            cp_commit();
            cp_wait1();
        } else {
            cp_wait0();
        }
        __syncthreads();

        uint32_t st = sb + (ch & 1) * STAGESZ;
#pragma unroll
        for (int kk = 0; kk < 32; kk += 16) {
            uint32_t ahi[4][4], alo[4][4];
#pragma unroll
            for (int i = 0; i < 4; i++) {
                uint32_t off = (a_row + i * 16) * PITCHB + (kk + a_kp) * 2;
                ldsm4(ahi[i][0], ahi[i][1], ahi[i][2], ahi[i][3], st + off);
                ldsm4(alo[i][0], alo[i][1], alo[i][2], alo[i][3], st + BUFSZ + off);
            }
#pragma unroll
            for (int j = 0; j < 4; j++) {
                uint32_t boff = (b_row + j * 8) * PITCHB + (kk + b_kp) * 2;
                uint32_t bh0, bh1, bl0, bl1;
                ldsm2(bh0, bh1, st + 2 * BUFSZ + boff);
                ldsm2(bl0, bl1, st + 3 * BUFSZ + boff);
#pragma unroll
                for (int i = 0; i < 4; i++) {
                    mma_bf16(acc[i][j], ahi[i], bh0, bh1);
                    mma_bf16(acc[i][j], ahi[i], bl0, bl1);
                    mma_bf16(acc[i][j], alo[i], bh0, bh1);
                }
            }
        }
        __syncthreads();
    }

    // --- epilogue: write C + fused alpha partial dots ---
    int crow = row0 + wm * 64 + (lane >> 2);
    int ccol_l = wn * 32 + (lane & 3) * 2;       // local col within tile (= within head)
    // a-vector values for this lane's 8 column pairs
    float as0[4], as1[4], ad0[4], ad1[4];
#pragma unroll
    for (int j = 0; j < 4; j++) {
        int c = hd * HID + ccol_l + j * 8;
        as0[j] = avec_s[c]; as1[j] = avec_s[c + 1];
        ad0[j] = avec_d[c]; ad1[j] = avec_d[c + 1];
    }
#pragma unroll
    for (int i = 0; i < 4; i++) {
        int r1 = crow + i * 16, r2 = r1 + 8;
        float s1 = 0.f, s2 = 0.f, d1 = 0.f, d2 = 0.f;
#pragma unroll
        for (int j = 0; j < 4; j++) {
            int cc = col0 + ccol_l + j * 8;
            if (r1 < N) *(float2*)(C + (size_t)r1 * M + cc) = make_float2(acc[i][j][0], acc[i][j][1]);
            if (r2 < N) *(float2*)(C + (size_t)r2 * M + cc) = make_float2(acc[i][j][2], acc[i][j][3]);
            s1 = fmaf(acc[i][j][0], as0[j], fmaf(acc[i][j][1], as1[j], s1));
            d1 = fmaf(acc[i][j][0], ad0[j], fmaf(acc[i][j][1], ad1[j], d1));
            s2 = fmaf(acc[i][j][2], as0[j], fmaf(acc[i][j][3], as1[j], s2));
            d2 = fmaf(acc[i][j][2], ad0[j], fmaf(acc[i][j][3], ad1[j], d2));
        }
        // quad reduce (lanes sharing the same row)
#pragma unroll
        for (int off = 1; off < 4; off <<= 1) {
            s1 += __shfl_xor_sync(0xffffffffu, s1, off);
            s2 += __shfl_xor_sync(0xffffffffu, s2, off);
            d1 += __shfl_xor_sync(0xffffffffu, d1, off);
            d2 += __shfl_xor_sync(0xffffffffu, d2, off);
        }
        if ((lane & 3) == 0) {
            if (r1 < N) { atomicAdd(&g_as[r1 * H + hd], s1); atomicAdd(&g_ad[r1 * H + hd], d1); }
            if (r2 < N) { atomicAdd(&g_as[r2 * H + hd], s2); atomicAdd(&g_ad[r2 * H + hd], d2); }
        }
    }
}

// ---------------- per-node segment softmax over incoming edges ----------------
template <int H>
__global__ void k_softmax(int N) {
    int n = blockIdx.x * (blockDim.x >> 5) + (threadIdx.x >> 5);
    int lane = threadIdx.x & 31;
    if (n >= N) return;
    int beg = g_rowptr[n], end = g_rowptr[n + 1];
    float adh[H], mx[H], sm[H];
#pragma unroll
    for (int h = 0; h < H; h++) {
        adh[h] = g_ad[n * H + h];
        mx[h] = -1e30f;
        sm[h] = 0.f;
    }
    for (int j = beg + lane; j < end; j += 32) {
        int s = g_col[j];
#pragma unroll
        for (int h = 0; h < H; h++) {
            float e = g_as[s * H + h] + adh[h];
            e = e > 0.f ? e : 0.2f * e;           // leaky relu
            g_w[(size_t)j * H + h] = e;
            mx[h] = fmaxf(mx[h], e);
        }
    }
#pragma unroll
    for (int h = 0; h < H; h++)
        for (int off = 16; off; off >>= 1)
            mx[h] = fmaxf(mx[h], __shfl_xor_sync(0xffffffffu, mx[h], off));
    for (int j = beg + lane; j < end; j += 32) {
#pragma unroll
        for (int h = 0; h < H; h++) {
            float ex = __expf(g_w[(size_t)j * H + h] - mx[h]);
            g_w[(size_t)j * H + h] = ex;
            sm[h] += ex;
        }
    }
#pragma unroll
    for (int h = 0; h < H; h++) {
        for (int off = 16; off; off >>= 1)
            sm[h] += __shfl_xor_sync(0xffffffffu, sm[h], off);
        sm[h] = 1.f / sm[h];
    }
    for (int j = beg + lane; j < end; j += 32) {
#pragma unroll
        for (int h = 0; h < H; h++) g_w[(size_t)j * H + h] *= sm[h];
    }
}

// ---------------- per-node weighted gather-aggregate + bias + elu -> split bf16 ----------------
// NT threads; thread t covers cols 4t..4t+3 (one float4), all within one head.
template <int H, int NT>
__global__ __launch_bounds__(NT) void k_aggregate(const float* __restrict__ hbuf,
                                                  const float* __restrict__ bias,
                                                  int N) {
    int n = blockIdx.x;
    if (n >= N) return;
    int t = threadIdx.x;
    int hd = (H == 4) ? (t >> 5) : 0;
    float4 acc = make_float4(0.f, 0.f, 0.f, 0.f);
    int beg = g_rowptr[n], end = g_rowptr[n + 1];
#pragma unroll 2
    for (int j = beg; j < end; j++) {
        int s = g_col[j];
        float w = g_w[(size_t)j * H + hd];
        float4 v = ((const float4*)(hbuf + (size_t)s * (H * HID)))[t];
        acc.x = fmaf(w, v.x, acc.x);
        acc.y = fmaf(w, v.y, acc.y);
        acc.z = fmaf(w, v.z, acc.z);
        acc.w = fmaf(w, v.w, acc.w);
    }
    float4 bv = ((const float4*)bias)[t];
    float o[4] = {acc.x + bv.x, acc.y + bv.y, acc.z + bv.z, acc.w + bv.w};
    ushort hi[4], lo[4];
#pragma unroll
    for (int q = 0; q < 4; q++) {
        float v = o[q] > 0.f ? o[q] : (__expf(o[q]) - 1.f);   // elu
        __nv_bfloat16 hv = __float2bfloat16(v);
        hi[q] = __bfloat16_as_ushort(hv);
        lo[q] = __bfloat16_as_ushort(__float2bfloat16(v - __bfloat162float(hv)));
    }
    size_t o4 = (size_t)n * (H * HID) + 4 * t;
    *(uint2*)(g_Ahi + o4) = make_uint2((uint32_t)hi[0] | ((uint32_t)hi[1] << 16),
                                       (uint32_t)hi[2] | ((uint32_t)hi[3] << 16));
    *(uint2*)(g_Alo + o4) = make_uint2((uint32_t)lo[0] | ((uint32_t)lo[1] << 16),
                                       (uint32_t)lo[2] | ((uint32_t)lo[3] << 16));
}

// ---------------- fc head: 16 nodes per 64-thread block (w1 L1-resident) ----------------
#define FC_NB 16
__global__ __launch_bounds__(64) void k_fc(const float* __restrict__ w1,
                                           const float* __restrict__ b1,
                                           const float* __restrict__ w2,
                                           const float* __restrict__ b2,
                                           float* __restrict__ out, int N) {
    __shared__ float xs[128];
    __shared__ float part[2];
    int t = threadIdx.x;   // 64
    float bias1 = b1[t];
    float wv2 = w2[t];
    float bias2 = b2[0];
    for (int it = 0; it < FC_NB; it++) {
        int n = blockIdx.x * FC_NB + it;
        if (n >= N) return;
        size_t base = (size_t)n * 128;
        xs[t]      = __bfloat162float(g_Ahi[base + t])      + __bfloat162float(g_Alo[base + t]);
        xs[t + 64] = __bfloat162float(g_Ahi[base + t + 64]) + __bfloat162float(g_Alo[base + t + 64]);
        __syncthreads();
        float d = bias1;
#pragma unroll 8
        for (int k = 0; k < 128; k++) d = fmaf(xs[k], w1[k * 64 + t], d);
        d = fmaxf(d, 0.f);
        float p = d * wv2;
        for (int off = 16; off; off >>= 1) p += __shfl_xor_sync(0xffffffffu, p, off);
        if ((t & 31) == 0) part[t >> 5] = p;
        __syncthreads();
        if (t == 0) out[n] = 1.f / (1.f + __expf(-(part[0] + part[1] + bias2)));
        __syncthreads();
    }
}

// ---------------- launch ----------------
extern "C" void kernel_launch(void* const* d_in, const int* in_sizes, int n_in,
                              void* d_out, int out_size) {
    const float* x      = (const float*)d_in[0];
    const int*   eidx   = (const int*)d_in[1];
    const float* W1     = (const float*)d_in[2];
    const float* a_src1 = (const float*)d_in[3];
    const float* a_dst1 = (const float*)d_in[4];
    const float* b1     = (const float*)d_in[5];
    const float* W2     = (const float*)d_in[6];
    const float* a_src2 = (const float*)d_in[7];
    const float* a_dst2 = (const float*)d_in[8];
    const float* b2     = (const float*)d_in[9];
    const float* W3     = (const float*)d_in[10];
    const float* a_src3 = (const float*)d_in[11];
    const float* a_dst3 = (const float*)d_in[12];
    const float* b3     = (const float*)d_in[13];
    const float* fc1w   = (const float*)d_in[14];
    const float* fc1b   = (const float*)d_in[15];
    const float* fc2w   = (const float*)d_in[16];
    const float* fc2b   = (const float*)d_in[17];
    float* out = (float*)d_out;

    int N = in_sizes[0] / 64;
    int E = in_sizes[1] / 2;
    const int* srcp = eidx;
    const int* dstp = eidx + E;

    float *Hb, *As, *Ad;
    __nv_bfloat16 *Whi, *Wlo, *Ahi, *Alo;
    cudaGetSymbolAddress((void**)&Hb, g_Hbuf);
    cudaGetSymbolAddress((void**)&Whi, g_Whi);
    cudaGetSymbolAddress((void**)&Wlo, g_Wlo);
    cudaGetSymbolAddress((void**)&Ahi, g_Ahi);
    cudaGetSymbolAddress((void**)&Alo, g_Alo);
    cudaGetSymbolAddress((void**)&As, g_as);
    cudaGetSymbolAddress((void**)&Ad, g_ad);

    const int GSMEM = 2 * STAGESZ;   // 81920
    static int s_attr_done = 0;
    if (!s_attr_done) {
        cudaFuncSetAttribute(k_gemm_mma, cudaFuncAttributeMaxDynamicSharedMemorySize, GSMEM);
        s_attr_done = 1;
    }

    int nb = (N + 1023) / 1024;
    int rowT = (N + 127) / 128;

    // CSR (dst-indexed) with self-loops
    k_init_deg<<<(N + 255) / 256, 256>>>(N);
    k_count<<<(E + 255) / 256, 256>>>(dstp, E);
    k_scan1<<<nb, 1024>>>(N);
    k_scan2<<<1, 64>>>(nb);
    k_scan3<<<(N + 255) / 256, 256>>>(N);
    k_fill_self<<<(N + 255) / 256, 256>>>(N);
    k_fill_edges<<<(E + 255) / 256, 256>>>(srcp, dstp, E);

    // Layer 1: h = x @ W1  [N,512], K=64
    k_asplit<<<(N * 64 + 255) / 256, 256>>>(x, N * 64);
    k_wsplit<<<(64 * 512 + 255) / 256, 256>>>(W1, 64, 512);
    cudaMemsetAsync(As, 0, (size_t)N * 4 * sizeof(float));
    cudaMemsetAsync(Ad, 0, (size_t)N * 4 * sizeof(float));
    k_gemm_mma<<<dim3(4, rowT), 256, GSMEM>>>(Ahi, Alo, Whi, Wlo, Hb, a_src1, a_dst1, N, 64, 512, 4);
    k_softmax<4><<<(N + 7) / 8, 256>>>(N);
    k_aggregate<4, 128><<<N, 128>>>(Hb, b1, N);

    // Layer 2: K=512, M=512
    k_wsplit<<<(512 * 512 + 255) / 256, 256>>>(W2, 512, 512);
    cudaMemsetAsync(As, 0, (size_t)N * 4 * sizeof(float));
    cudaMemsetAsync(Ad, 0, (size_t)N * 4 * sizeof(float));
    k_gemm_mma<<<dim3(4, rowT), 256, GSMEM>>>(Ahi, Alo, Whi, Wlo, Hb, a_src2, a_dst2, N, 512, 512, 4);
    k_softmax<4><<<(N + 7) / 8, 256>>>(N);
    k_aggregate<4, 128><<<N, 128>>>(Hb, b2, N);

    // Layer 3: K=512, M=128 (heads=1)
    k_wsplit<<<(512 * 128 + 255) / 256, 256>>>(W3, 512, 128);
    cudaMemsetAsync(As, 0, (size_t)N * sizeof(float));
    cudaMemsetAsync(Ad, 0, (size_t)N * sizeof(float));
    k_gemm_mma<<<dim3(1, rowT), 256, GSMEM>>>(Ahi, Alo, Whi, Wlo, Hb, a_src3, a_dst3, N, 512, 128, 1);
    k_softmax<1><<<(N + 7) / 8, 256>>>(N);
    k_aggregate<1, 32><<<N, 32>>>(Hb, b3, N);

    // MLP head
    k_fc<<<(N + FC_NB - 1) / FC_NB, 64>>>(fc1w, fc1b, fc2w, fc2b, out, N);
}